// round 10
// baseline (speedup 1.0000x reference)
#include <cuda_runtime.h>
#include <cstdint>

// CTC loss forward: T=2048, N=64, C=256, S=256, E=2S+1=513.
// One CTA per batch element. Alpha in EXTENDED-RANGE LINEAR domain
// (mant in [1,2), int32 exponent; alignment via exponent bit ops; one EX2
// per state-step, off the dependency chain).
// R10: TWO timesteps per __syncthreads. Each warp covers 30 net states with
// a 2-lane halo (lane l -> state 30*warp + l - 2). Step t reads old alpha
// from SMEM; step t+1 takes s-1/s-2 from __shfl_up of step-t registers.
// Intermediate alpha never hits SMEM; barriers halved.
// Prefetch warp (last warp) fetches 2 rows/round via cp.async ring.

#define Tdim 2048
#define Nb   64
#define Cdim 256
#define Sdim 256
#define Edim (2 * Sdim + 1)   // 513
#define AWARPS 18             // alpha warps: 18*30 = 540 >= 513 states
#define THREADS ((AWARPS + 1) * 32)   // 608; last warp = prefetch
#define DEPTH 6               // cp.async ring depth (rows of x)

#define LOG2E 1.4426950408889634f
#define LN2   0.6931471805599453f
#define NEGL  (-1.0e30f)
#define BIGE  (-(1 << 28))    // exponent of the zero state
#define FULL  0xffffffffu

__device__ float g_block_loss[Nb];

__device__ __forceinline__ void cp_async16(uint32_t saddr, const void* gaddr) {
    asm volatile("cp.async.cg.shared.global [%0], [%1], 16;\n"
                 :: "r"(saddr), "l"(gaddr));
}
__device__ __forceinline__ void cp_commit() {
    asm volatile("cp.async.commit_group;\n");
}
template <int N>
__device__ __forceinline__ void cp_wait() {
    asm volatile("cp.async.wait_group %0;\n" :: "n"(N));
}

// 2^d for d <= 0, exact; d <= -127 -> 0.0f (matches reference's exp underflow).
__device__ __forceinline__ float pow2i(int d) {
    d = max(d, -127);
    return __int_as_float((d + 127) << 23);
}

// One alpha update in (mant, exp) form. Inputs: own (om,oe), s-1 (m2,e2),
// s-2 (m3,e3) pre-masked by skip, and p (linear). Outputs new (mant, exp).
__device__ __forceinline__ void alpha_step(float om, int oe, float m2, int e2,
                                           float m3, int e3, float p,
                                           float& rm, int& re) {
    const int em = max(oe, max(e2, e3));
    float sum = om * pow2i(oe - em);
    sum = fmaf(m2, pow2i(e2 - em), sum);
    sum = fmaf(m3, pow2i(e3 - em), sum);
    const float v = sum * p;
    const int vb = __float_as_int(v);
    re = em + ((vb >> 23) - 127);
    rm = __int_as_float((vb & 0x007fffff) | 0x3f800000);
    if (v == 0.f) { rm = 0.f; re = BIGE; }
}

__global__ __launch_bounds__(THREADS, 1)
void ctc_alpha_kernel(const float* __restrict__ x,
                      const int*   __restrict__ y,
                      const int*   __restrict__ ilen,
                      const int*   __restrict__ tlen)
{
    __shared__ __align__(16) float xrow[DEPTH][Cdim];   // ring of log-prob rows
    __shared__ __align__(16) float2 bufA[2 + Edim];     // pads [0..1] = zero state
    __shared__ __align__(16) float2 bufB[2 + Edim];

    const int n    = blockIdx.x;
    const int tid  = threadIdx.x;
    const int wid  = tid >> 5;
    const int lane = tid & 31;
    const int L    = tlen[n];
    const int En   = 2 * L + 1;
    const int len  = ilen[n];

    // Lane -> state mapping with 2-lane halo.
    const int  s      = 30 * wid + lane - 2;       // may be <0 or >=En
    const bool pf     = (wid == AWARPS);           // prefetch warp
    const bool active = !pf && (s >= 0) && (s < En);
    const bool owner  = active && (lane >= 2);     // stores its state

    int  lab = 0;
    bool sk  = false;
    if (active && (s & 1)) {
        lab = y[n * Sdim + (s >> 1)];
        if (s >= 3) sk = (lab != y[n * Sdim + ((s - 2) >> 1)]);
    }

    // Zero-init both alpha buffers (incl. pads and states >= En).
    const float2 ZERO2 = make_float2(0.f, __int_as_float(BIGE));
    for (int i = tid; i < 2 + Edim; i += THREADS) { bufA[i] = ZERO2; bufB[i] = ZERO2; }

    const float*   xbase   = x + (size_t)n * Cdim;
    const size_t   rstride = (size_t)Nb * Cdim;
    const uint32_t sxrow   = (uint32_t)__cvta_generic_to_shared(&xrow[0][0]);

    // ---- Prologue: prefetch rows 0..4 (one group per row) ----
    if (pf) {
        #pragma unroll
        for (int r = 0; r < 5; ++r) {
            const float* g = xbase + (size_t)r * rstride + lane * 8;
            uint32_t     a = sxrow + (uint32_t)(r * Cdim + lane * 8) * 4;
            cp_async16(a,      g);
            cp_async16(a + 16, g + 4);
            cp_commit();
        }
        cp_wait<2>();   // rows 0,1,2 complete; rows 3,4 pending
    }
    __syncthreads();

    // alpha_0 init: states 0,1 -> (mant, exp) from log2 value
    if (tid <= 1 && tid < En) {
        const int   c  = (tid == 0) ? 0 : y[n * Sdim];
        const float a0 = xrow[0][c] * LOG2E;
        const float fe = floorf(a0);
        bufA[2 + tid] = make_float2(exp2f(a0 - fe), __int_as_float((int)fe));
    }
    __syncthreads();   // publish alpha_0

    float2* Acur  = bufA;
    float2* Bnext = bufB;

    // Own alpha registers (owners keep them live across rounds).
    float a_m = 0.f; int a_e = BIGE;
    if (active) { float2 o = Acur[2 + s]; a_m = o.x; a_e = __float_as_int(o.y); }

    int t      = 1;
    int slot0  = 1, slot1 = 2;   // slots of rows t, t+1
    int pslot0 = 5, pslot1 = 0;  // slots of rows t+4, t+5

    // ---- Main loop: 2 timesteps per barrier ----
    while (t + 1 < len) {
        // step 1 (time t): inputs from SMEM (published last barrier)
        float m1 = 0.f; int e1 = BIGE;
        if (active) {
            const float p1 = exp2f(xrow[slot0][lab] * LOG2E);
            float om = a_m; int oe = a_e;
            if (lane < 2) { float2 o = Acur[2 + s]; om = o.x; oe = __float_as_int(o.y); }
            const float2 q1 = Acur[1 + s];   // s-1
            const float2 q2 = Acur[s];       // s-2
            const int   e2 = __float_as_int(q1.y);
            const int   e3 = sk ? __float_as_int(q2.y) : BIGE;
            const float m3 = sk ? q2.x : 0.f;
            alpha_step(om, oe, q1.x, e2, m3, e3, p1, m1, e1);
        }

        // halo exchange of step-1 results (all lanes of alpha warps converged)
        const float sm1 = __shfl_up_sync(FULL, m1, 1);
        const int   se1 = __shfl_up_sync(FULL, e1, 1);
        const float sm2 = __shfl_up_sync(FULL, m1, 2);
        const int   se2 = __shfl_up_sync(FULL, e1, 2);

        // step 2 (time t+1): inputs from registers/shuffles; owners store
        if (owner) {
            const float p2 = exp2f(xrow[slot1][lab] * LOG2E);
            const int   e3 = sk ? se2 : BIGE;
            const float m3 = sk ? sm2 : 0.f;
            float m2n; int e2n;
            alpha_step(m1, e1, sm1, se1, m3, e3, p2, m2n, e2n);
            Bnext[2 + s] = make_float2(m2n, __int_as_float(e2n));
            a_m = m2n; a_e = e2n;
        }

        // prefetch rows t+4, t+5 (pf warp); steady state: 2 groups pending
        if (pf) {
            int r0 = t + 4; if (r0 > Tdim - 1) r0 = Tdim - 1;
            int r1 = t + 5; if (r1 > Tdim - 1) r1 = Tdim - 1;
            const float* g0 = xbase + (size_t)r0 * rstride + lane * 8;
            uint32_t     a0 = sxrow + (uint32_t)(pslot0 * Cdim + lane * 8) * 4;
            cp_async16(a0,      g0);
            cp_async16(a0 + 16, g0 + 4);
            cp_commit();
            const float* g1 = xbase + (size_t)r1 * rstride + lane * 8;
            uint32_t     a1 = sxrow + (uint32_t)(pslot1 * Cdim + lane * 8) * 4;
            cp_async16(a1,      g1);
            cp_async16(a1 + 16, g1 + 4);
            cp_commit();
            cp_wait<2>();   // rows t+2, t+3 complete
        }

        __syncthreads();    // publish Bnext (time t+1) and rows t+2, t+3

        t += 2;
        slot0  += 2; if (slot0  >= DEPTH) slot0  -= DEPTH;
        slot1  += 2; if (slot1  >= DEPTH) slot1  -= DEPTH;
        pslot0 += 2; if (pslot0 >= DEPTH) pslot0 -= DEPTH;
        pslot1 += 2; if (pslot1 >= DEPTH) pslot1 -= DEPTH;

        float2* tmp = Acur; Acur = Bnext; Bnext = tmp;
    }

    // ---- Odd tail: one SMEM-only step (row t guaranteed present) ----
    if (t < len) {
        if (owner) {
            const float p1 = exp2f(xrow[slot0][lab] * LOG2E);
            const float2 q1 = Acur[1 + s];
            const float2 q2 = Acur[s];
            const int   e2 = __float_as_int(q1.y);
            const int   e3 = sk ? __float_as_int(q2.y) : BIGE;
            const float m3 = sk ? q2.x : 0.f;
            float mn; int en;
            alpha_step(a_m, a_e, q1.x, e2, m3, e3, p1, mn, en);
            Bnext[2 + s] = make_float2(mn, __int_as_float(en));
        }
        __syncthreads();
        float2* tmp = Acur; Acur = Bnext; Bnext = tmp;
    }

    if (tid == 0) {
        const float2 A1 = Acur[2 + (2 * L - 1)];
        const float2 A2 = Acur[2 + 2 * L];
        const float l1 = (A1.x == 0.f) ? NEGL
                         : (float)__float_as_int(A1.y) + log2f(A1.x);
        const float l2 = (A2.x == 0.f) ? NEGL
                         : (float)__float_as_int(A2.y) + log2f(A2.x);
        const float m  = fmaxf(l1, l2);
        const float ll2 = m + log2f(exp2f(l1 - m) + exp2f(l2 - m));
        g_block_loss[n] = -(ll2 * LN2) / (float)L;
    }
}

__global__ void ctc_reduce_kernel(float* __restrict__ out)
{
    const int tid = threadIdx.x;   // 64 threads
    float v = g_block_loss[tid];
    #pragma unroll
    for (int off = 16; off > 0; off >>= 1)
        v += __shfl_xor_sync(0xffffffffu, v, off);
    __shared__ float w[2];
    if ((tid & 31) == 0) w[tid >> 5] = v;
    __syncthreads();
    if (tid == 0) out[0] = (w[0] + w[1]) * (1.0f / (float)Nb);
}

extern "C" void kernel_launch(void* const* d_in, const int* in_sizes, int n_in,
                              void* d_out, int out_size)
{
    (void)in_sizes; (void)n_in; (void)out_size;
    const float* x  = (const float*)d_in[0];
    const int*   y  = (const int*)d_in[1];
    const int*   il = (const int*)d_in[2];
    const int*   tl = (const int*)d_in[3];

    ctc_alpha_kernel<<<Nb, THREADS>>>(x, y, il, tl);
    ctc_reduce_kernel<<<1, 64>>>((float*)d_out);
}

// round 16
// speedup vs baseline: 1.0231x; 1.0231x over previous
#include <cuda_runtime.h>
#include <cstdint>

// CTC loss forward: T=2048, N=64, C=256, S=256, E=2S+1=513.
// One CTA per batch element. Alpha in EXTENDED-RANGE LINEAR domain
// (mant in [1,2), int32 exponent; alignment via exponent bit ops).
// TWO STATES PER THREAD (pair = even blank + odd label) x TWO TIMESTEPS
// per barrier. Even states never use s-2 (blank => skip false), so the only
// external input per pair is state 2i-1: one LDS.64 per round, one STS.128,
// two SHFLs for the intra-round halo. 9 alpha warps + 1 prefetch warp.
// Lane 0 of each warp is a redundant halo pair (reloads own pair from SMEM
// each round; its own step-t+1 result is discarded). Odd halves >= En masked.
// R16: sixth submission (R11-R15 never executed; infra). Four clean audits.

#define Tdim 2048
#define Nb   64
#define Cdim 256
#define Sdim 256
#define Edim (2 * Sdim + 1)   // 513
#define AWARPS 9              // alpha warps; pairs i = 31*w + lane - 1
#define THREADS ((AWARPS + 1) * 32)   // 320; warp 9 = prefetch
#define DEPTH 6               // cp.async ring depth (rows of x)
#define BUFSZ (2 + Edim + 1)  // pads [0..1] + 513 states + 1 (float4 stores)

#define LOG2E 1.4426950408889634f
#define LN2   0.6931471805599453f
#define NEGL  (-1.0e30f)
#define BIGE  (-(1 << 28))    // exponent of the zero state
#define FULL  0xffffffffu

__device__ float g_block_loss[Nb];

__device__ __forceinline__ void cp_async16(uint32_t saddr, const void* gaddr) {
    asm volatile("cp.async.cg.shared.global [%0], [%1], 16;\n"
                 :: "r"(saddr), "l"(gaddr));
}
__device__ __forceinline__ void cp_commit() {
    asm volatile("cp.async.commit_group;\n");
}
template <int N>
__device__ __forceinline__ void cp_wait() {
    asm volatile("cp.async.wait_group %0;\n" :: "n"(N));
}

// 2^d for d <= 0, exact; d <= -127 -> 0.0f (matches reference exp underflow).
__device__ __forceinline__ float pow2i(int d) {
    d = max(d, -127);
    return __int_as_float((d + 127) << 23);
}

// 2-term extended-range update: v = (a1 + a2) * p, renormalized.
__device__ __forceinline__ void step2(float a1m, int a1e, float a2m, int a2e,
                                      float p, float& rm, int& re) {
    const int em = max(a1e, a2e);
    float sum = a1m * pow2i(a1e - em);
    sum = fmaf(a2m, pow2i(a2e - em), sum);
    const float v = sum * p;
    const int vb = __float_as_int(v);
    re = em + ((vb >> 23) - 127);
    rm = __int_as_float((vb & 0x007fffff) | 0x3f800000);
    if (v == 0.f) { rm = 0.f; re = BIGE; }
}

// 3-term extended-range update: v = (a1 + a2 + a3) * p, renormalized.
__device__ __forceinline__ void step3(float a1m, int a1e, float a2m, int a2e,
                                      float a3m, int a3e, float p,
                                      float& rm, int& re) {
    const int em = max(a1e, max(a2e, a3e));
    float sum = a1m * pow2i(a1e - em);
    sum = fmaf(a2m, pow2i(a2e - em), sum);
    sum = fmaf(a3m, pow2i(a3e - em), sum);
    const float v = sum * p;
    const int vb = __float_as_int(v);
    re = em + ((vb >> 23) - 127);
    rm = __int_as_float((vb & 0x007fffff) | 0x3f800000);
    if (v == 0.f) { rm = 0.f; re = BIGE; }
}

__global__ __launch_bounds__(THREADS, 1)
void ctc_alpha_kernel(const float* __restrict__ x,
                      const int*   __restrict__ y,
                      const int*   __restrict__ ilen,
                      const int*   __restrict__ tlen)
{
    __shared__ __align__(16) float  xrow[DEPTH][Cdim];  // ring of log-prob rows
    __shared__ __align__(16) float2 bufA[BUFSZ];
    __shared__ __align__(16) float2 bufB[BUFSZ];

    const int n    = blockIdx.x;
    const int tid  = threadIdx.x;
    const int wid  = tid >> 5;
    const int lane = tid & 31;
    const int L    = tlen[n];
    const int En   = 2 * L + 1;
    const int len  = ilen[n];

    const bool pf = (wid == AWARPS);
    const int  i  = 31 * wid + lane - 1;   // pair index; lane 0 = halo
    const int  s0 = 2 * i;                 // even (blank) state
    const int  s1 = 2 * i + 1;             // odd (label) state

    const bool activeT = !pf && (i >= 0) && (s0 < En);
    const bool owner   = activeT && (lane >= 1);
    const bool live1   = activeT && (s1 < En);

    int  lab = 0;
    bool sk  = false;
    if (live1) {
        lab = y[n * Sdim + i];
        if (i >= 1) sk = (lab != y[n * Sdim + i - 1]);
    }

    // Zero-init both buffers (pads + all states + spare).
    const float2 ZERO2 = make_float2(0.f, __int_as_float(BIGE));
    for (int k = tid; k < BUFSZ; k += THREADS) { bufA[k] = ZERO2; bufB[k] = ZERO2; }

    const float*   xbase   = x + (size_t)n * Cdim;
    const size_t   rstride = (size_t)Nb * Cdim;
    const uint32_t sxrow   = (uint32_t)__cvta_generic_to_shared(&xrow[0][0]);

    // ---- Prologue: prefetch rows 0..4 (one group per row) ----
    if (pf) {
        #pragma unroll
        for (int r = 0; r < 5; ++r) {
            const float* g = xbase + (size_t)r * rstride + lane * 8;
            uint32_t     a = sxrow + (uint32_t)(r * Cdim + lane * 8) * 4;
            cp_async16(a,      g);
            cp_async16(a + 16, g + 4);
            cp_commit();
        }
        cp_wait<2>();   // rows 0,1,2 complete; rows 3,4 pending
    }
    __syncthreads();

    // alpha_0 init: states 0,1
    if (tid < 2) {
        const int   c  = (tid == 0) ? 0 : y[n * Sdim];
        const float a0 = xrow[0][c] * LOG2E;
        const float fe = floorf(a0);
        bufA[2 + tid] = make_float2(exp2f(a0 - fe), __int_as_float((int)fe));
    }
    __syncthreads();   // publish alpha_0

    float2* Acur  = bufA;
    float2* Bnext = bufB;

    // Own pair in registers (states s0, s1 at current time).
    float o_m0 = 0.f, o_m1 = 0.f; int o_e0 = BIGE, o_e1 = BIGE;
    if (activeT) {
        float4 ow = reinterpret_cast<const float4*>(Acur)[i + 1];
        o_m0 = ow.x; o_e0 = __float_as_int(ow.y);
        o_m1 = ow.z; o_e1 = __float_as_int(ow.w);
    }

    int t = 1;
    int slot0 = 1, slot1 = 2;    // ring slots of rows t, t+1
    int pslot0 = 5, pslot1 = 0;  // ring slots for rows t+4, t+5

    // ---- Main loop: 2 timesteps per barrier ----
    while (t + 1 < len) {
        float t_m0 = 0.f, t_m1 = 0.f; int t_e0 = BIGE, t_e1 = BIGE;

        if (!pf) {
            // neighbor: state 2i-1 at time t-1 (published last barrier)
            float nbm = 0.f; int nbe = BIGE;
            if (activeT) {
                const float2 nb = Acur[2 + s0 - 1];   // buf index 2i+1
                nbm = nb.x; nbe = __float_as_int(nb.y);
                if (lane == 0) {   // halo: own regs stale, reload pair
                    float4 ow = reinterpret_cast<const float4*>(Acur)[i + 1];
                    o_m0 = ow.x; o_e0 = __float_as_int(ow.y);
                    o_m1 = ow.z; o_e1 = __float_as_int(ow.w);
                }
            }

            // probabilities (EX2 off the dependency chain)
            const float pb0 = exp2f(xrow[slot0][0]   * LOG2E);
            const float pb1 = exp2f(xrow[slot1][0]   * LOG2E);
            const float pl0 = exp2f(xrow[slot0][lab] * LOG2E);
            const float pl1 = exp2f(xrow[slot1][lab] * LOG2E);

            // step t
            if (activeT) {
                step2(o_m0, o_e0, nbm, nbe, pb0, t_m0, t_e0);
                const float a3m = sk ? nbm : 0.f;
                const int   a3e = sk ? nbe : BIGE;
                step3(o_m1, o_e1, o_m0, o_e0, a3m, a3e, pl0, t_m1, t_e1);
                if (!live1) { t_m1 = 0.f; t_e1 = BIGE; }
            }

            // halo exchange: lane-1's odd state (2i-1) at time t
            const float s_m1 = __shfl_up_sync(FULL, t_m1, 1);
            const int   s_e1 = __shfl_up_sync(FULL, t_e1, 1);

            // step t+1
            if (activeT) {
                float u_m0, u_m1; int u_e0, u_e1;
                step2(t_m0, t_e0, s_m1, s_e1, pb1, u_m0, u_e0);
                const float a3m = sk ? s_m1 : 0.f;
                const int   a3e = sk ? s_e1 : BIGE;
                step3(t_m1, t_e1, t_m0, t_e0, a3m, a3e, pl1, u_m1, u_e1);
                if (!live1) { u_m1 = 0.f; u_e1 = BIGE; }
                if (owner) {
                    reinterpret_cast<float4*>(Bnext)[i + 1] =
                        make_float4(u_m0, __int_as_float(u_e0),
                                    u_m1, __int_as_float(u_e1));
                }
                o_m0 = u_m0; o_e0 = u_e0; o_m1 = u_m1; o_e1 = u_e1;
            }
        } else {
            // prefetch rows t+4, t+5; steady state: 2 groups pending after wait
            int r0 = t + 4; if (r0 > Tdim - 1) r0 = Tdim - 1;
            int r1 = t + 5; if (r1 > Tdim - 1) r1 = Tdim - 1;
            const float* g0 = xbase + (size_t)r0 * rstride + lane * 8;
            uint32_t     a0 = sxrow + (uint32_t)(pslot0 * Cdim + lane * 8) * 4;
            cp_async16(a0,      g0);
            cp_async16(a0 + 16, g0 + 4);
            cp_commit();
            const float* g1 = xbase + (size_t)r1 * rstride + lane * 8;
            uint32_t     a1 = sxrow + (uint32_t)(pslot1 * Cdim + lane * 8) * 4;
            cp_async16(a1,      g1);
            cp_async16(a1 + 16, g1 + 4);
            cp_commit();
            cp_wait<2>();   // rows t+2, t+3 complete
        }

        __syncthreads();    // publish Bnext (time t+1) and rows t+2, t+3

        t += 2;
        slot0  += 2; if (slot0  >= DEPTH) slot0  -= DEPTH;
        slot1  += 2; if (slot1  >= DEPTH) slot1  -= DEPTH;
        pslot0 += 2; if (pslot0 >= DEPTH) pslot0 -= DEPTH;
        pslot1 += 2; if (pslot1 >= DEPTH) pslot1 -= DEPTH;

        float2* tmp = Acur; Acur = Bnext; Bnext = tmp;
    }

    // ---- Odd tail: one step, all inputs from SMEM ----
    if (t < len) {
        if (activeT) {
            const float4 ow = reinterpret_cast<const float4*>(Acur)[i + 1];
            const float2 nb = Acur[2 + s0 - 1];
            const float  pb = exp2f(xrow[slot0][0]   * LOG2E);
            const float  pl = exp2f(xrow[slot0][lab] * LOG2E);
            const float om0 = ow.x; const int oe0 = __float_as_int(ow.y);
            const float om1 = ow.z; const int oe1 = __float_as_int(ow.w);
            const float nbm = nb.x; const int nbe = __float_as_int(nb.y);
            float u_m0, u_m1; int u_e0, u_e1;
            step2(om0, oe0, nbm, nbe, pb, u_m0, u_e0);
            const float a3m = sk ? nbm : 0.f;
            const int   a3e = sk ? nbe : BIGE;
            step3(om1, oe1, om0, oe0, a3m, a3e, pl, u_m1, u_e1);
            if (!live1) { u_m1 = 0.f; u_e1 = BIGE; }
            if (owner) {
                reinterpret_cast<float4*>(Bnext)[i + 1] =
                    make_float4(u_m0, __int_as_float(u_e0),
                                u_m1, __int_as_float(u_e1));
            }
        }
        __syncthreads();
        float2* tmp = Acur; Acur = Bnext; Bnext = tmp;
    }

    if (tid == 0) {
        const float2 A1 = Acur[2 + (2 * L - 1)];
        const float2 A2 = Acur[2 + 2 * L];
        const float l1 = (A1.x == 0.f) ? NEGL
                         : (float)__float_as_int(A1.y) + log2f(A1.x);
        const float l2 = (A2.x == 0.f) ? NEGL
                         : (float)__float_as_int(A2.y) + log2f(A2.x);
        const float m  = fmaxf(l1, l2);
        const float ll2 = m + log2f(exp2f(l1 - m) + exp2f(l2 - m));
        g_block_loss[n] = -(ll2 * LN2) / (float)L;
    }
}

__global__ void ctc_reduce_kernel(float* __restrict__ out)
{
    const int tid = threadIdx.x;   // 64 threads
    float v = g_block_loss[tid];
    #pragma unroll
    for (int off = 16; off > 0; off >>= 1)
        v += __shfl_xor_sync(0xffffffffu, v, off);
    __shared__ float w[2];
    if ((tid & 31) == 0) w[tid >> 5] = v;
    __syncthreads();
    if (tid == 0) out[0] = (w[0] + w[1]) * (1.0f / (float)Nb);
}

extern "C" void kernel_launch(void* const* d_in, const int* in_sizes, int n_in,
                              void* d_out, int out_size)
{
    (void)in_sizes; (void)n_in; (void)out_size;
    const float* x  = (const float*)d_in[0];
    const int*   y  = (const int*)d_in[1];
    const int*   il = (const int*)d_in[2];
    const int*   tl = (const int*)d_in[3];

    ctc_alpha_kernel<<<Nb, THREADS>>>(x, y, il, tl);
    ctc_reduce_kernel<<<1, 64>>>((float*)d_out);
}